// round 1
// baseline (speedup 1.0000x reference)
#include <cuda_runtime.h>

#define IC_   128
#define OC_   128
#define KS_   3
#define ZDIM_ 256
#define B_    16
#define H_    64
#define W_    64
#define WSIZE_ (OC_ * IC_ * KS_ * KS_)   // 147456

// Scratch for per-sample weights: base + delta  (9.44 MB, static device array)
__device__ float g_w[(size_t)B_ * WSIZE_];

// ---------------------------------------------------------------------------
// Kernel 1: per-sample weight generation
//   g_w[b][m] = base_w[m] + head_b[m] + sum_d z[b][d] * head_w[m][d]
// Block: 256 threads, M_TILE = 256 rows of head_w, all 16 batches.
// Thread: 4 m (interleaved stride 64) x 4 b -> 16 FFMA per 8 scalar LDS.
// ---------------------------------------------------------------------------
__global__ __launch_bounds__(256) void weight_kernel(
    const float* __restrict__ z,       // [16, 256]
    const float* __restrict__ base_w,  // [147456]
    const float* __restrict__ head_w,  // [147456, 256]
    const float* __restrict__ head_b)  // [147456]
{
    __shared__ float z_s[B_ * ZDIM_];     // 16 KB
    __shared__ float hw_s[256 * 17];      // 256 m x 16 d, pitch 17 (conflict-free)

    const int tid = threadIdx.x;
    const int m0  = blockIdx.x * 256;

    // load z once (small)
    for (int i = tid; i < B_ * ZDIM_; i += 256) z_s[i] = z[i];

    const int mg = tid & 63;   // 0..63  -> m = m0 + mg + 64*i
    const int bg = tid >> 6;   // 0..3   -> b = bg*4 + j

    float acc[4][4];
#pragma unroll
    for (int i = 0; i < 4; i++)
#pragma unroll
        for (int j = 0; j < 4; j++) acc[i][j] = 0.f;

    for (int dc = 0; dc < 16; dc++) {
        __syncthreads();
        // cooperative load of head_w tile: 256 m x 16 d (float4, coalesced)
#pragma unroll
        for (int k = 0; k < 4; k++) {
            int t4 = tid + k * 256;     // 0..1023
            int m  = t4 >> 2;           // 0..255
            int d4 = t4 & 3;            // 0..3
            float4 v = *reinterpret_cast<const float4*>(
                &head_w[(size_t)(m0 + m) * ZDIM_ + dc * 16 + d4 * 4]);
            float* dst = &hw_s[m * 17 + d4 * 4];
            dst[0] = v.x; dst[1] = v.y; dst[2] = v.z; dst[3] = v.w;
        }
        __syncthreads();

#pragma unroll
        for (int d = 0; d < 16; d++) {
            float hv[4], zv[4];
#pragma unroll
            for (int i = 0; i < 4; i++) hv[i] = hw_s[(mg + 64 * i) * 17 + d];
#pragma unroll
            for (int j = 0; j < 4; j++) zv[j] = z_s[(bg * 4 + j) * ZDIM_ + dc * 16 + d];
#pragma unroll
            for (int i = 0; i < 4; i++)
#pragma unroll
                for (int j = 0; j < 4; j++)
                    acc[i][j] += hv[i] * zv[j];
        }
    }

#pragma unroll
    for (int i = 0; i < 4; i++) {
        int m = m0 + mg + 64 * i;
        float bb = base_w[m] + head_b[m];
#pragma unroll
        for (int j = 0; j < 4; j++) {
            int b = bg * 4 + j;
            g_w[(size_t)b * WSIZE_ + m] = bb + acc[i][j];
        }
    }
}

// ---------------------------------------------------------------------------
// Kernel 2: per-sample 3x3 conv, fp32, SMEM-tiled shifted GEMM.
// Block: (b, oc-tile of 64, pixel-tile of 128 = 2 rows x 64 cols), 256 threads.
// Thread: 4 oc x 8 pixels (pixels interleaved stride 16 -> conflict-free LDS).
// Inner step (per ic,kh,kw): 8 x-LDS + 4 w-LDS feeding 32 FFMA.
// ---------------------------------------------------------------------------
__global__ __launch_bounds__(256) void conv_kernel(
    const float* __restrict__ x,   // [16, 128, 64, 64]
    float* __restrict__ out)       // [16, 128, 64, 64]
{
    __shared__ float x_s[8][4][68];   // 8 ic x 4 rows x 66(+2 pad) cols
    __shared__ float w_s[72 * 65];    // (ic*9+j) rows x 64 oc, pitch 65

    const int tid = threadIdx.x;
    const int pt  = blockIdx.x;        // 0..31 : pixel tile (2 output rows)
    const int ocb = blockIdx.y * 64;   // 0 or 64
    const int b   = blockIdx.z;        // 0..15

    const int r0  = pt * 2;            // first output row of tile
    const int pg  = tid & 15;          // pixel group 0..15
    const int ocg = tid >> 4;          // oc group  0..15

    float acc[4][8];
#pragma unroll
    for (int i = 0; i < 4; i++)
#pragma unroll
        for (int k = 0; k < 8; k++) acc[i][k] = 0.f;

    for (int ic0 = 0; ic0 < IC_; ic0 += 8) {
        __syncthreads();
        // ---- load x slab: 8 ic x 4 rows(r0-1..r0+2) x 66 cols(-1..64), zero-padded
        for (int idx = tid; idx < 8 * 4 * 66; idx += 256) {
            int ic  = idx / 264;
            int rem = idx % 264;
            int rr  = rem / 66;
            int cc  = rem % 66;
            int gr  = r0 - 1 + rr;
            int gc  = cc - 1;
            float v = 0.f;
            if ((unsigned)gr < 64u && (unsigned)gc < 64u)
                v = x[(((size_t)b * IC_ + ic0 + ic) * H_ + gr) * W_ + gc];
            x_s[ic][rr][cc] = v;
        }
        // ---- load weights: 64 oc x (8 ic x 9 taps), transposed to [tap][oc]
        for (int idx = tid; idx < 64 * 72; idx += 256) {
            int oc = idx / 72;
            int r  = idx % 72;   // ic_local*9 + j
            w_s[r * 65 + oc] =
                g_w[((size_t)b * OC_ + ocb + oc) * (IC_ * 9) + (size_t)ic0 * 9 + r];
        }
        __syncthreads();

        for (int ic = 0; ic < 8; ic++) {
#pragma unroll
            for (int kh = 0; kh < 3; kh++) {
#pragma unroll
                for (int kw = 0; kw < 3; kw++) {
                    float wv[4];
                    const float* wp = &w_s[(ic * 9 + kh * 3 + kw) * 65 + ocg * 4];
#pragma unroll
                    for (int i = 0; i < 4; i++) wv[i] = wp[i];
                    float xv[8];
#pragma unroll
                    for (int k = 0; k < 8; k++) {
                        int rowl = (k >> 2) + kh;               // 0..3
                        int coll = pg + 16 * (k & 3) + kw;      // 0..65
                        xv[k] = x_s[ic][rowl][coll];
                    }
#pragma unroll
                    for (int i = 0; i < 4; i++)
#pragma unroll
                        for (int k = 0; k < 8; k++)
                            acc[i][k] += wv[i] * xv[k];
                }
            }
        }
    }

    // ---- store 4 oc x 8 pixels, coalesced across pg
    const int p0 = pt * 128;
#pragma unroll
    for (int i = 0; i < 4; i++) {
        int oc = ocb + ocg * 4 + i;
        float* op = &out[(((size_t)b * OC_ + oc) * (H_ * W_)) + p0];
#pragma unroll
        for (int k = 0; k < 8; k++)
            op[pg + 16 * k] = acc[i][k];
    }
}

// ---------------------------------------------------------------------------
// Inputs (metadata order): x, z, base_weight, head_w, head_b. Output: fp32.
// ---------------------------------------------------------------------------
extern "C" void kernel_launch(void* const* d_in, const int* in_sizes, int n_in,
                              void* d_out, int out_size) {
    const float* x      = (const float*)d_in[0];
    const float* z      = (const float*)d_in[1];
    const float* base_w = (const float*)d_in[2];
    const float* head_w = (const float*)d_in[3];
    const float* head_b = (const float*)d_in[4];
    float* out = (float*)d_out;

    weight_kernel<<<WSIZE_ / 256, 256>>>(z, base_w, head_w, head_b);
    conv_kernel<<<dim3(32, 2, 16), 256>>>(x, out);
}

// round 3
// speedup vs baseline: 2.3162x; 2.3162x over previous
#include <cuda_runtime.h>
#include <cstdint>

#define IC_   128
#define OC_   128
#define ZDIM_ 256
#define B_    16
#define WSIZE_ (OC_ * IC_ * 9)   // 147456

// Per-sample weights, layout [b][tap][oc][ic], tf32-rounded fp32 (9.44 MB)
__device__ float g_w[(size_t)B_ * WSIZE_];

__device__ __forceinline__ float to_tf32(float v) {
    float o;
    asm("cvt.rna.tf32.f32 %0, %1;" : "=f"(o) : "f"(v));
    return o;
}

// ---------------------------------------------------------------------------
// Kernel 1: per-sample weight generation (fp32 GEMM on CUDA cores)
//   g_w[b][tap][oc][ic] = tf32_round(base_w[m] + head_b[m] + head_w[m] . z[b])
//   where m = (oc*128 + ic)*9 + tap
// ---------------------------------------------------------------------------
__global__ __launch_bounds__(256) void weight_kernel(
    const float* __restrict__ z, const float* __restrict__ base_w,
    const float* __restrict__ head_w, const float* __restrict__ head_b)
{
    __shared__ float z_s[B_ * ZDIM_];
    __shared__ float hw_s[256 * 17];

    const int tid = threadIdx.x;
    const int m0  = blockIdx.x * 256;

    for (int i = tid; i < B_ * ZDIM_; i += 256) z_s[i] = z[i];

    const int mg = tid & 63;
    const int bg = tid >> 6;

    float acc[4][4];
#pragma unroll
    for (int i = 0; i < 4; i++)
#pragma unroll
        for (int j = 0; j < 4; j++) acc[i][j] = 0.f;

    for (int dc = 0; dc < 16; dc++) {
        __syncthreads();
#pragma unroll
        for (int k = 0; k < 4; k++) {
            int t4 = tid + k * 256;
            int m  = t4 >> 2;
            int d4 = t4 & 3;
            float4 v = *reinterpret_cast<const float4*>(
                &head_w[(size_t)(m0 + m) * ZDIM_ + dc * 16 + d4 * 4]);
            float* dst = &hw_s[m * 17 + d4 * 4];
            dst[0] = v.x; dst[1] = v.y; dst[2] = v.z; dst[3] = v.w;
        }
        __syncthreads();
#pragma unroll
        for (int d = 0; d < 16; d++) {
            float hv[4], zv[4];
#pragma unroll
            for (int i = 0; i < 4; i++) hv[i] = hw_s[(mg + 64 * i) * 17 + d];
#pragma unroll
            for (int j = 0; j < 4; j++) zv[j] = z_s[(bg * 4 + j) * ZDIM_ + dc * 16 + d];
#pragma unroll
            for (int i = 0; i < 4; i++)
#pragma unroll
                for (int j = 0; j < 4; j++)
                    acc[i][j] += hv[i] * zv[j];
        }
    }

#pragma unroll
    for (int i = 0; i < 4; i++) {
        int m   = m0 + mg + 64 * i;
        int oc  = m / 1152;
        int rem = m - oc * 1152;
        int ic  = rem / 9;
        int tap = rem - ic * 9;
        float bb = base_w[m] + head_b[m];
        size_t o0 = (size_t)(tap << 14) + (oc << 7) + ic;
#pragma unroll
        for (int j = 0; j < 4; j++) {
            int b = bg * 4 + j;
            g_w[(size_t)b * WSIZE_ + o0] = to_tf32(bb + acc[i][j]);
        }
    }
}

// ---------------------------------------------------------------------------
// Kernel 2: implicit-GEMM conv on mma.sync tf32 (HMMA).
// CTA tile: M=128 oc x N=128 px (2 rows x 64 cols) x K=1152 (36 chunks of 32).
// 8 warps 4x2: each 32 oc x 64 px. Fragments from XOR-swizzled SMEM.
// x staged per-icc into x_s (tf32-rounded once, reused by 9 taps).
// SMEM floats: A0=0, A1=4096, B0=8192, B1=12288, XS=16384 (32*4*68=8704)
// ---------------------------------------------------------------------------
#define SM_FLOATS (16384 + 8704)

__device__ __forceinline__ void mma_tf32(float* d, const uint32_t* a,
                                         uint32_t b0, uint32_t b1) {
    asm volatile(
        "mma.sync.aligned.m16n8k8.row.col.f32.tf32.tf32.f32 "
        "{%0,%1,%2,%3}, {%4,%5,%6,%7}, {%8,%9}, {%0,%1,%2,%3};"
        : "+f"(d[0]), "+f"(d[1]), "+f"(d[2]), "+f"(d[3])
        : "r"(a[0]), "r"(a[1]), "r"(a[2]), "r"(a[3]), "r"(b0), "r"(b1));
}

__global__ __launch_bounds__(256, 2) void conv_kernel(
    const float* __restrict__ x, float* __restrict__ out)
{
    extern __shared__ float sm[];
    float* xs = sm + 16384;

    const int tid  = threadIdx.x;
    const int wid  = tid >> 5;
    const int lid  = tid & 31;
    const int g    = lid >> 2;        // 0..7
    const int tg   = lid & 3;         // 0..3
    const int wm   = wid & 3;         // oc quarter
    const int wn   = wid >> 2;        // px half
    const int pair = blockIdx.x;      // 0..31
    const int b    = blockIdx.y;      // 0..15
    const int r0   = pair * 2;

    const float* xb = x + (size_t)b * IC_ * 4096;
    const float* wb = g_w + (size_t)b * WSIZE_;

    float acc[2][8][4];
#pragma unroll
    for (int mt = 0; mt < 2; mt++)
#pragma unroll
        for (int nt = 0; nt < 8; nt++)
#pragma unroll
            for (int r = 0; r < 4; r++) acc[mt][nt][r] = 0.f;

    // ---- helpers as lambdas ----
    auto build_xs = [&](int icc) {
        // x_s[ic32][row4][68]: rows r0-1..r0+2, cols -1..64, zero-padded, tf32
        for (int idx = tid; idx < 32 * 4 * 66; idx += 256) {
            int ic  = idx / 264;
            int rem = idx - ic * 264;
            int rr  = rem / 66;
            int cc  = rem - rr * 66;
            int gr  = r0 - 1 + rr;
            int gc  = cc - 1;
            float v = 0.f;
            if ((unsigned)gr < 64u && (unsigned)gc < 64u)
                v = xb[(size_t)(icc * 32 + ic) * 4096 + gr * 64 + gc];
            xs[ic * 272 + rr * 68 + cc] = to_tf32(v);
        }
    };

    auto build_chunk = [&](int j, float* As, float* Bs) {
        int icc = j / 9;
        int tap = j - icc * 9;
        int kh  = tap / 3;
        int kw  = tap - kh * 3;
        // A: [oc128][ic32], swizzle col^=4*(oc&7)
        const float* wsrc = wb + ((size_t)tap << 14) + icc * 32;
#pragma unroll
        for (int t = 0; t < 4; t++) {
            int idx = tid + 256 * t;          // 0..1023
            int oc  = idx >> 3;
            int q   = idx & 7;
            float4 v = *reinterpret_cast<const float4*>(wsrc + (oc << 7) + q * 4);
            int col = (q * 4) ^ ((oc & 7) * 4);
            *reinterpret_cast<float4*>(As + oc * 32 + col) = v;
        }
        // B: [k32][n128], swizzle n^=8*(k&3); from x_s
#pragma unroll
        for (int t = 0; t < 4; t++) {
            int idx = tid + 256 * t;          // 0..1023
            int k   = idx >> 5;               // 0..31
            int q   = idx & 31;
            int n0  = q * 4;
            int rowl = (n0 >> 6) + kh;        // 0..3
            int col  = (n0 & 63) + kw;        // 0..65
            const float* xp = xs + k * 272 + rowl * 68 + col;
            float4 v = make_float4(xp[0], xp[1], xp[2], xp[3]);
            int nsw = n0 ^ ((k & 3) * 8);
            *reinterpret_cast<float4*>(Bs + k * 128 + nsw) = v;
        }
    };

    auto mma_chunk = [&](const float* As, const float* Bs) {
#pragma unroll
        for (int ks = 0; ks < 4; ks++) {
            uint32_t a[2][4];
            int k0 = ks * 8 + tg;
            int sw = g * 4;
#pragma unroll
            for (int mt = 0; mt < 2; mt++) {
                int m = wm * 32 + mt * 16 + g;
                a[mt][0] = __float_as_uint(As[m * 32 + (k0 ^ sw)]);
                a[mt][1] = __float_as_uint(As[(m + 8) * 32 + (k0 ^ sw)]);
                a[mt][2] = __float_as_uint(As[m * 32 + ((k0 + 4) ^ sw)]);
                a[mt][3] = __float_as_uint(As[(m + 8) * 32 + ((k0 + 4) ^ sw)]);
            }
#pragma unroll
            for (int nt = 0; nt < 8; nt++) {
                int n  = wn * 64 + nt * 8 + g;
                int bs = n ^ (tg * 8);
                uint32_t b0 = __float_as_uint(Bs[k0 * 128 + bs]);
                uint32_t b1 = __float_as_uint(Bs[(k0 + 4) * 128 + bs]);
                mma_tf32(acc[0][nt], a[0], b0, b1);
                mma_tf32(acc[1][nt], a[1], b0, b1);
            }
        }
    };

    // ---- pipelined main loop ----
    build_xs(0);
    __syncthreads();
    build_chunk(0, sm, sm + 8192);

    for (int j = 0; j < 36; j++) {
        if (j + 1 < 36) {
            if (((j + 1) % 9) == 0) {
                __syncthreads();
                build_xs((j + 1) / 9);
                __syncthreads();
            }
            float* As = sm + ((j + 1) & 1) * 4096;
            float* Bs = sm + 8192 + ((j + 1) & 1) * 4096;
            build_chunk(j + 1, As, Bs);
        }
        __syncthreads();   // builds of chunk j (and j+1) visible
        mma_chunk(sm + (j & 1) * 4096, sm + 8192 + (j & 1) * 4096);
        __syncthreads();   // all reads of buf j done before overwrite
    }

    // ---- epilogue: acc -> out[b][oc][px] ----
#pragma unroll
    for (int mt = 0; mt < 2; mt++) {
        int oc = wm * 32 + mt * 16 + g;
#pragma unroll
        for (int nt = 0; nt < 8; nt++) {
            int n  = wn * 64 + nt * 8 + 2 * tg;
            size_t base = ((size_t)b * OC_ + oc) * 4096 + pair * 128 + n;
            float2 v0 = make_float2(acc[mt][nt][0], acc[mt][nt][1]);
            float2 v1 = make_float2(acc[mt][nt][2], acc[mt][nt][3]);
            *reinterpret_cast<float2*>(out + base)            = v0;
            *reinterpret_cast<float2*>(out + base + 8 * 4096) = v1;
        }
    }
}

// ---------------------------------------------------------------------------
extern "C" void kernel_launch(void* const* d_in, const int* in_sizes, int n_in,
                              void* d_out, int out_size) {
    const float* x      = (const float*)d_in[0];
    const float* z      = (const float*)d_in[1];
    const float* base_w = (const float*)d_in[2];
    const float* head_w = (const float*)d_in[3];
    const float* head_b = (const float*)d_in[4];
    float* out = (float*)d_out;

    static bool attr_set = false;
    if (!attr_set) {
        cudaFuncSetAttribute(conv_kernel,
                             cudaFuncAttributeMaxDynamicSharedMemorySize,
                             SM_FLOATS * 4);
        attr_set = true;
    }

    weight_kernel<<<WSIZE_ / 256, 256>>>(z, base_w, head_w, head_b);
    conv_kernel<<<dim3(32, 16), 256, SM_FLOATS * 4>>>(x, out);
}

// round 4
// speedup vs baseline: 2.7452x; 1.1853x over previous
#include <cuda_runtime.h>
#include <cstdint>

#define IC_   128
#define OC_   128
#define ZDIM_ 256
#define B_    16
#define WSIZE_ (OC_ * IC_ * 9)   // 147456

// Per-sample weights, layout [b][tap][oc][ic], tf32-rounded fp32 (9.44 MB)
__device__ float g_w[(size_t)B_ * WSIZE_];

__device__ __forceinline__ float to_tf32(float v) {
    float o;
    asm("cvt.rna.tf32.f32 %0, %1;" : "=f"(o) : "f"(v));
    return o;
}

// ---------------------------------------------------------------------------
// Kernel 1: per-sample weight generation (fp32 GEMM on CUDA cores)
//   g_w[b][tap][oc][ic] = tf32_round(base_w[m] + head_b[m] + head_w[m] . z[b])
//   where m = (oc*128 + ic)*9 + tap
// ---------------------------------------------------------------------------
__global__ __launch_bounds__(256) void weight_kernel(
    const float* __restrict__ z, const float* __restrict__ base_w,
    const float* __restrict__ head_w, const float* __restrict__ head_b)
{
    __shared__ float z_s[B_ * ZDIM_];
    __shared__ float hw_s[256 * 17];

    const int tid = threadIdx.x;
    const int m0  = blockIdx.x * 256;

    for (int i = tid; i < B_ * ZDIM_; i += 256) z_s[i] = z[i];

    const int mg = tid & 63;
    const int bg = tid >> 6;

    float acc[4][4];
#pragma unroll
    for (int i = 0; i < 4; i++)
#pragma unroll
        for (int j = 0; j < 4; j++) acc[i][j] = 0.f;

    for (int dc = 0; dc < 16; dc++) {
        __syncthreads();
#pragma unroll
        for (int k = 0; k < 4; k++) {
            int t4 = tid + k * 256;
            int m  = t4 >> 2;
            int d4 = t4 & 3;
            float4 v = *reinterpret_cast<const float4*>(
                &head_w[(size_t)(m0 + m) * ZDIM_ + dc * 16 + d4 * 4]);
            float* dst = &hw_s[m * 17 + d4 * 4];
            dst[0] = v.x; dst[1] = v.y; dst[2] = v.z; dst[3] = v.w;
        }
        __syncthreads();
#pragma unroll
        for (int d = 0; d < 16; d++) {
            float hv[4], zv[4];
#pragma unroll
            for (int i = 0; i < 4; i++) hv[i] = hw_s[(mg + 64 * i) * 17 + d];
#pragma unroll
            for (int j = 0; j < 4; j++) zv[j] = z_s[(bg * 4 + j) * ZDIM_ + dc * 16 + d];
#pragma unroll
            for (int i = 0; i < 4; i++)
#pragma unroll
                for (int j = 0; j < 4; j++)
                    acc[i][j] += hv[i] * zv[j];
        }
    }

#pragma unroll
    for (int i = 0; i < 4; i++) {
        int m   = m0 + mg + 64 * i;
        int oc  = m / 1152;
        int rem = m - oc * 1152;
        int ic  = rem / 9;
        int tap = rem - ic * 9;
        float bb = base_w[m] + head_b[m];
        size_t o0 = (size_t)(tap << 14) + (oc << 7) + ic;
#pragma unroll
        for (int j = 0; j < 4; j++) {
            int b = bg * 4 + j;
            g_w[(size_t)b * WSIZE_ + o0] = to_tf32(bb + acc[i][j]);
        }
    }
}

// ---------------------------------------------------------------------------
// Kernel 2: implicit-GEMM conv on mma.sync tf32 (HMMA).
// CTA tile: M=128 oc x N=128 px (2 rows x 64 cols) x K=1152 (36 chunks of 32).
// 8 warps 4x2: each 32 oc x 64 px.
// A: 3-stage SMEM ring, XOR-4 swizzle, single barrier per chunk.
// B: NO staging — fragments load directly from the xs slab (tf32-rounded x,
//    rows r0-1..r0+2, cols -1..64). ic-stride padded to 280 floats so lanes
//    hit banks 24*tg + g (mod 32): conflict-free.
// SMEM floats: A stages 0..12288, XS at 12288 (32*280 = 8960). Total 21248.
// ---------------------------------------------------------------------------
#define XS_OFF    12288
#define SM_FLOATS (12288 + 32 * 280)

__device__ __forceinline__ void mma_tf32(float* d, const uint32_t* a,
                                         uint32_t b0, uint32_t b1) {
    asm volatile(
        "mma.sync.aligned.m16n8k8.row.col.f32.tf32.tf32.f32 "
        "{%0,%1,%2,%3}, {%4,%5,%6,%7}, {%8,%9}, {%0,%1,%2,%3};"
        : "+f"(d[0]), "+f"(d[1]), "+f"(d[2]), "+f"(d[3])
        : "r"(a[0]), "r"(a[1]), "r"(a[2]), "r"(a[3]), "r"(b0), "r"(b1));
}

__global__ __launch_bounds__(256, 2) void conv_kernel(
    const float* __restrict__ x, float* __restrict__ out)
{
    extern __shared__ float sm[];
    float* xs = sm + XS_OFF;

    const int tid  = threadIdx.x;
    const int wid  = tid >> 5;
    const int lid  = tid & 31;
    const int g    = lid >> 2;        // 0..7
    const int tg   = lid & 3;         // 0..3
    const int wm   = wid & 3;         // oc quarter (32 oc)
    const int wn   = wid >> 2;        // px half (64 px = 1 output row)
    const int pair = blockIdx.x;      // 0..31
    const int b    = blockIdx.y;      // 0..15
    const int r0   = pair * 2;

    const float* xb = x + (size_t)b * IC_ * 4096;
    const float* wb = g_w + (size_t)b * WSIZE_;

    float acc[2][8][4];
#pragma unroll
    for (int mt = 0; mt < 2; mt++)
#pragma unroll
        for (int nt = 0; nt < 8; nt++)
#pragma unroll
            for (int r = 0; r < 4; r++) acc[mt][nt][r] = 0.f;

    auto build_xs = [&](int icc) {
        // xs[ic][rr][cc]: rows r0-1..r0+2, cols -1..64, zero-padded, tf32.
        for (int idx = tid; idx < 32 * 4 * 66; idx += 256) {
            int ic  = idx / 264;
            int rem = idx - ic * 264;
            int rr  = rem / 66;
            int cc  = rem - rr * 66;
            int gr  = r0 - 1 + rr;
            int gc  = cc - 1;
            float v = 0.f;
            if ((unsigned)gr < 64u && (unsigned)gc < 64u)
                v = xb[(size_t)(icc * 32 + ic) * 4096 + gr * 64 + gc];
            xs[ic * 280 + rr * 68 + cc] = to_tf32(v);
        }
    };

    auto build_A = [&](int j, float* As) {
        int icc = j / 9;
        int tap = j - icc * 9;
        const float* wsrc = wb + ((size_t)tap << 14) + icc * 32;
#pragma unroll
        for (int t = 0; t < 4; t++) {
            int idx = tid + 256 * t;          // 0..1023
            int oc  = idx >> 3;
            int q   = idx & 7;
            float4 v = *reinterpret_cast<const float4*>(wsrc + (oc << 7) + q * 4);
            int col = (q * 4) ^ ((oc & 7) * 4);
            *reinterpret_cast<float4*>(As + oc * 32 + col) = v;
        }
    };

    auto mma_chunk = [&](const float* As, int kh, int kw) {
        // B base for this warp: row (wn+kh), col offset kw, lane col +g
        const float* xw = xs + (wn + kh) * 68 + kw + g;
        const int   sw  = g * 4;
#pragma unroll
        for (int ks = 0; ks < 4; ks++) {
            const int k0 = ks * 8 + tg;
            uint32_t a[2][4];
#pragma unroll
            for (int mt = 0; mt < 2; mt++) {
                int m = wm * 32 + mt * 16 + g;
                a[mt][0] = __float_as_uint(As[m * 32 + (k0 ^ sw)]);
                a[mt][1] = __float_as_uint(As[(m + 8) * 32 + (k0 ^ sw)]);
                a[mt][2] = __float_as_uint(As[m * 32 + ((k0 + 4) ^ sw)]);
                a[mt][3] = __float_as_uint(As[(m + 8) * 32 + ((k0 + 4) ^ sw)]);
            }
            const float* xk0 = xw + k0 * 280;
            const float* xk1 = xk0 + 4 * 280;
#pragma unroll
            for (int nt = 0; nt < 8; nt++) {
                uint32_t b0 = __float_as_uint(xk0[nt * 8]);
                uint32_t b1 = __float_as_uint(xk1[nt * 8]);
                mma_tf32(acc[0][nt], a[0], b0, b1);
                mma_tf32(acc[1][nt], a[1], b0, b1);
            }
        }
    };

    // ---- prologue ----
    build_xs(0);
    build_A(0, sm);
    __syncthreads();

    // ---- main loop: one barrier per chunk (3-stage A ring) ----
    for (int j = 0; j < 36; j++) {
        const float* As = sm + (j % 3) * 4096;
        int icc = j / 9;
        int tap = j - icc * 9;
        int kh  = tap / 3;
        int kw  = tap - kh * 3;

        if (j + 1 < 36) {
            build_A(j + 1, sm + ((j + 1) % 3) * 4096);
            __syncthreads();
            mma_chunk(As, kh, kw);
            if (((j + 1) % 9) == 0) {
                // xs rebuild: must happen after mma(j) (reads old xs) on all warps
                __syncthreads();
                build_xs((j + 1) / 9);
                __syncthreads();
            }
        } else {
            mma_chunk(As, kh, kw);
        }
    }

    // ---- epilogue: acc -> out[b][oc][px] ----
#pragma unroll
    for (int mt = 0; mt < 2; mt++) {
        int oc = wm * 32 + mt * 16 + g;
#pragma unroll
        for (int nt = 0; nt < 8; nt++) {
            int n  = wn * 64 + nt * 8 + 2 * tg;
            size_t base = ((size_t)b * OC_ + oc) * 4096 + pair * 128 + n;
            float2 v0 = make_float2(acc[mt][nt][0], acc[mt][nt][1]);
            float2 v1 = make_float2(acc[mt][nt][2], acc[mt][nt][3]);
            *reinterpret_cast<float2*>(out + base)            = v0;
            *reinterpret_cast<float2*>(out + base + 8 * 4096) = v1;
        }
    }
}

// ---------------------------------------------------------------------------
extern "C" void kernel_launch(void* const* d_in, const int* in_sizes, int n_in,
                              void* d_out, int out_size) {
    const float* x      = (const float*)d_in[0];
    const float* z      = (const float*)d_in[1];
    const float* base_w = (const float*)d_in[2];
    const float* head_w = (const float*)d_in[3];
    const float* head_b = (const float*)d_in[4];
    float* out = (float*)d_out;

    static bool attr_set = false;
    if (!attr_set) {
        cudaFuncSetAttribute(conv_kernel,
                             cudaFuncAttributeMaxDynamicSharedMemorySize,
                             SM_FLOATS * 4);
        attr_set = true;
    }

    weight_kernel<<<WSIZE_ / 256, 256>>>(z, base_w, head_w, head_b);
    conv_kernel<<<dim3(32, 16), 256, SM_FLOATS * 4>>>(x, out);
}

// round 5
// speedup vs baseline: 2.7869x; 1.0152x over previous
#include <cuda_runtime.h>
#include <cstdint>

#define IC_   128
#define OC_   128
#define ZDIM_ 256
#define B_    16
#define WSIZE_ (OC_ * IC_ * 9)   // 147456

// Per-sample weights, layout [b][tap][oc][ic], tf32-rounded fp32 (9.44 MB)
__device__ float g_w[(size_t)B_ * WSIZE_];

__device__ __forceinline__ float to_tf32(float v) {
    float o;
    asm("cvt.rna.tf32.f32 %0, %1;" : "=f"(o) : "f"(v));
    return o;
}

// ---------------------------------------------------------------------------
// Kernel 1: per-sample weight generation (fp32 GEMM on CUDA cores)
//   g_w[b][tap][oc][ic] = tf32_round(base_w[m] + head_b[m] + head_w[m] . z[b])
//   where m = (oc*128 + ic)*9 + tap
// Pipelined: LDG(tile j+2) -> regs while computing tile j; 1 barrier/iter.
// ---------------------------------------------------------------------------
__global__ __launch_bounds__(256) void weight_kernel(
    const float* __restrict__ z, const float* __restrict__ base_w,
    const float* __restrict__ head_w, const float* __restrict__ head_b)
{
    __shared__ float zt[ZDIM_ * B_];        // z transposed: [d][b], 16 KB
    __shared__ float hw_s[2][256 * 17];     // double-buffered head_w tile

    const int tid = threadIdx.x;
    const int m0  = blockIdx.x * 256;

    // z transposed load (broadcast-friendly)
    for (int i = tid; i < B_ * ZDIM_; i += 256) {
        int b = i >> 8;          // original [b][d]
        int d = i & 255;
        zt[d * B_ + b] = z[i];
    }

    const int mg = tid & 63;
    const int bg = tid >> 6;

    float acc[4][4];
#pragma unroll
    for (int i = 0; i < 4; i++)
#pragma unroll
        for (int j = 0; j < 4; j++) acc[i][j] = 0.f;

    // prefetch helpers: each thread owns 4 float4 of the 256x16 tile
    float4 ar[4];
    auto ldg_tile = [&](int dc) {
#pragma unroll
        for (int k = 0; k < 4; k++) {
            int t4 = tid + k * 256;
            int m  = t4 >> 2;
            int d4 = t4 & 3;
            ar[k] = *reinterpret_cast<const float4*>(
                &head_w[(size_t)(m0 + m) * ZDIM_ + dc * 16 + d4 * 4]);
        }
    };
    auto sts_tile = [&](int buf) {
#pragma unroll
        for (int k = 0; k < 4; k++) {
            int t4 = tid + k * 256;
            int m  = t4 >> 2;
            int d4 = t4 & 3;
            float* dst = &hw_s[buf][m * 17 + d4 * 4];
            dst[0] = ar[k].x; dst[1] = ar[k].y; dst[2] = ar[k].z; dst[3] = ar[k].w;
        }
    };

    ldg_tile(0);
    sts_tile(0);
    ldg_tile(1);
    __syncthreads();

    for (int dc = 0; dc < 16; dc++) {
        const float* hb = hw_s[dc & 1];
#pragma unroll
        for (int d = 0; d < 16; d++) {
            float hv[4];
#pragma unroll
            for (int i = 0; i < 4; i++) hv[i] = hb[(mg + 64 * i) * 17 + d];
            float4 zv = *reinterpret_cast<const float4*>(
                &zt[(dc * 16 + d) * B_ + bg * 4]);
            float zz[4] = {zv.x, zv.y, zv.z, zv.w};
#pragma unroll
            for (int i = 0; i < 4; i++)
#pragma unroll
                for (int j = 0; j < 4; j++)
                    acc[i][j] += hv[i] * zz[j];
        }
        if (dc < 15) {
            sts_tile((dc + 1) & 1);
            if (dc + 2 < 16) ldg_tile(dc + 2);
            __syncthreads();
        }
    }

#pragma unroll
    for (int i = 0; i < 4; i++) {
        int m   = m0 + mg + 64 * i;
        int oc  = m / 1152;
        int rem = m - oc * 1152;
        int ic  = rem / 9;
        int tap = rem - ic * 9;
        float bb = base_w[m] + head_b[m];
        size_t o0 = (size_t)(tap << 14) + (oc << 7) + ic;
#pragma unroll
        for (int j = 0; j < 4; j++) {
            int b = bg * 4 + j;
            g_w[(size_t)b * WSIZE_ + o0] = to_tf32(bb + acc[i][j]);
        }
    }
}

// ---------------------------------------------------------------------------
// Kernel 2: implicit-GEMM conv on mma.sync tf32 (HMMA).
// CTA tile: M=128 oc x N=128 px (2 rows x 64 cols) x K=1152 (36 chunks of 32).
// 8 warps 4x2: each 32 oc x 64 px.
// A: 2-stage SMEM ring; LDG(j+2)->regs prefetch, STS after mma, 1 barrier/chunk.
// B: direct from xs slab (tf32-rounded x, rows r0-1..r0+2, cols -1..64),
//    ic-stride 280 -> conflict-free fragment loads.
// SMEM floats: A 2x4096, XS at 8192 (32*280 = 8960). Total 17152 (67 KB).
// ---------------------------------------------------------------------------
#define XS_OFF    8192
#define SM_FLOATS (8192 + 32 * 280)

__device__ __forceinline__ void mma_tf32(float* d, const uint32_t* a,
                                         uint32_t b0, uint32_t b1) {
    asm volatile(
        "mma.sync.aligned.m16n8k8.row.col.f32.tf32.tf32.f32 "
        "{%0,%1,%2,%3}, {%4,%5,%6,%7}, {%8,%9}, {%0,%1,%2,%3};"
        : "+f"(d[0]), "+f"(d[1]), "+f"(d[2]), "+f"(d[3])
        : "r"(a[0]), "r"(a[1]), "r"(a[2]), "r"(a[3]), "r"(b0), "r"(b1));
}

__global__ __launch_bounds__(256, 2) void conv_kernel(
    const float* __restrict__ x, float* __restrict__ out)
{
    extern __shared__ float sm[];
    float* xs = sm + XS_OFF;

    const int tid  = threadIdx.x;
    const int wid  = tid >> 5;
    const int lid  = tid & 31;
    const int g    = lid >> 2;        // 0..7
    const int tg   = lid & 3;         // 0..3
    const int wm   = wid & 3;         // oc quarter (32 oc)
    const int wn   = wid >> 2;        // px half (64 px = 1 output row)
    const int pair = blockIdx.x;      // 0..31
    const int b    = blockIdx.y;      // 0..15
    const int r0   = pair * 2;

    const float* xb = x + (size_t)b * IC_ * 4096;
    const float* wb = g_w + (size_t)b * WSIZE_;

    float acc[2][8][4];
#pragma unroll
    for (int mt = 0; mt < 2; mt++)
#pragma unroll
        for (int nt = 0; nt < 8; nt++)
#pragma unroll
            for (int r = 0; r < 4; r++) acc[mt][nt][r] = 0.f;

    auto build_xs = [&](int icc) {
        for (int idx = tid; idx < 32 * 4 * 66; idx += 256) {
            int ic  = idx / 264;
            int rem = idx - ic * 264;
            int rr  = rem / 66;
            int cc  = rem - rr * 66;
            int gr  = r0 - 1 + rr;
            int gc  = cc - 1;
            float v = 0.f;
            if ((unsigned)gr < 64u && (unsigned)gc < 64u)
                v = xb[(size_t)(icc * 32 + ic) * 4096 + gr * 64 + gc];
            xs[ic * 280 + rr * 68 + cc] = to_tf32(v);
        }
    };

    // A prefetch: 4 float4 per thread per chunk
    float4 ar[4];
    const int a_oc = tid >> 3;            // 0..127 (base, +0 only since 256*4=1024 rows of 8)
    const int a_q  = tid & 7;
    auto ldg_A = [&](int j) {
        int icc = j / 9;
        int tap = j - icc * 9;
        const float* wsrc = wb + ((size_t)tap << 14) + icc * 32;
#pragma unroll
        for (int t = 0; t < 4; t++) {
            int idx = tid + 256 * t;
            int oc  = idx >> 3;
            int q   = idx & 7;
            ar[t] = *reinterpret_cast<const float4*>(wsrc + (oc << 7) + q * 4);
        }
    };
    auto sts_A = [&](float* As) {
#pragma unroll
        for (int t = 0; t < 4; t++) {
            int idx = tid + 256 * t;
            int oc  = idx >> 3;
            int q   = idx & 7;
            int col = (q * 4) ^ ((oc & 7) * 4);
            *reinterpret_cast<float4*>(As + oc * 32 + col) = ar[t];
        }
    };

    auto mma_chunk = [&](const float* As, int kh, int kw) {
        const float* xw = xs + (wn + kh) * 68 + kw + g;
        const int   sw  = g * 4;
#pragma unroll
        for (int ks = 0; ks < 4; ks++) {
            const int k0 = ks * 8 + tg;
            uint32_t a[2][4];
#pragma unroll
            for (int mt = 0; mt < 2; mt++) {
                int m = wm * 32 + mt * 16 + g;
                a[mt][0] = __float_as_uint(As[m * 32 + (k0 ^ sw)]);
                a[mt][1] = __float_as_uint(As[(m + 8) * 32 + (k0 ^ sw)]);
                a[mt][2] = __float_as_uint(As[m * 32 + ((k0 + 4) ^ sw)]);
                a[mt][3] = __float_as_uint(As[(m + 8) * 32 + ((k0 + 4) ^ sw)]);
            }
            const float* xk0 = xw + k0 * 280;
            const float* xk1 = xk0 + 4 * 280;
#pragma unroll
            for (int nt = 0; nt < 8; nt++) {
                uint32_t b0 = __float_as_uint(xk0[nt * 8]);
                uint32_t b1 = __float_as_uint(xk1[nt * 8]);
                mma_tf32(acc[0][nt], a[0], b0, b1);
                mma_tf32(acc[1][nt], a[1], b0, b1);
            }
        }
    };

    // ---- prologue ----
    build_xs(0);
    ldg_A(0);
    sts_A(sm);
    ldg_A(1);
    __syncthreads();

    // ---- main loop: 1 barrier per chunk, LDG two chunks ahead ----
    for (int j = 0; j < 36; j++) {
        int icc = j / 9;
        int tap = j - icc * 9;
        int kh  = tap / 3;
        int kw  = tap - kh * 3;

        mma_chunk(sm + (j & 1) * 4096, kh, kw);

        if (j + 1 < 36) {
            sts_A(sm + ((j + 1) & 1) * 4096);   // regs hold chunk j+1
            if (j + 2 < 36) ldg_A(j + 2);
            __syncthreads();
            if (((j + 1) % 9) == 0) {
                build_xs((j + 1) / 9);
                __syncthreads();
            }
        }
    }

    // ---- epilogue: acc -> out[b][oc][px] ----
#pragma unroll
    for (int mt = 0; mt < 2; mt++) {
        int oc = wm * 32 + mt * 16 + g;
#pragma unroll
        for (int nt = 0; nt < 8; nt++) {
            int n  = wn * 64 + nt * 8 + 2 * tg;
            size_t base = ((size_t)b * OC_ + oc) * 4096 + pair * 128 + n;
            float2 v0 = make_float2(acc[mt][nt][0], acc[mt][nt][1]);
            float2 v1 = make_float2(acc[mt][nt][2], acc[mt][nt][3]);
            *reinterpret_cast<float2*>(out + base)            = v0;
            *reinterpret_cast<float2*>(out + base + 8 * 4096) = v1;
        }
    }
}

// ---------------------------------------------------------------------------
extern "C" void kernel_launch(void* const* d_in, const int* in_sizes, int n_in,
                              void* d_out, int out_size) {
    const float* x      = (const float*)d_in[0];
    const float* z      = (const float*)d_in[1];
    const float* base_w = (const float*)d_in[2];
    const float* head_w = (const float*)d_in[3];
    const float* head_b = (const float*)d_in[4];
    float* out = (float*)d_out;

    static bool attr_set = false;
    if (!attr_set) {
        cudaFuncSetAttribute(conv_kernel,
                             cudaFuncAttributeMaxDynamicSharedMemorySize,
                             SM_FLOATS * 4);
        attr_set = true;
    }

    weight_kernel<<<WSIZE_ / 256, 256>>>(z, base_w, head_w, head_b);
    conv_kernel<<<dim3(32, 16), 256, SM_FLOATS * 4>>>(x, out);
}

// round 6
// speedup vs baseline: 2.8723x; 1.0307x over previous
#include <cuda_runtime.h>
#include <cstdint>

#define IC_   128
#define OC_   128
#define ZDIM_ 256
#define B_    16
#define WSIZE_ (OC_ * IC_ * 9)   // 147456

// Per-sample weights in m16n8k8 A-fragment order:
// [b][chunk j=icc*9+tap (36)][m16-tile (8)][ks (4)][lane (32)][reg (4)]
__device__ float g_w[(size_t)B_ * WSIZE_];

__device__ __forceinline__ float to_tf32(float v) {
    float o;
    asm("cvt.rna.tf32.f32 %0, %1;" : "=f"(o) : "f"(v));
    return o;
}

// ---------------------------------------------------------------------------
// Kernel 1: per-sample weight generation (fp32 GEMM on CUDA cores)
//   val = tf32_round(base_w[m] + head_b[m] + head_w[m] . z[b]),
//   scattered into fragment-order g_w.
// ---------------------------------------------------------------------------
__global__ __launch_bounds__(256) void weight_kernel(
    const float* __restrict__ z, const float* __restrict__ base_w,
    const float* __restrict__ head_w, const float* __restrict__ head_b)
{
    __shared__ float zt[ZDIM_ * B_];        // z transposed: [d][b]
    __shared__ float hw_s[2][256 * 20];     // double-buffered, pitch 20 (16B-aligned)

    const int tid = threadIdx.x;
    const int m0  = blockIdx.x * 256;

    for (int i = tid; i < B_ * ZDIM_; i += 256) {
        int b = i >> 8;
        int d = i & 255;
        zt[d * B_ + b] = z[i];
    }

    const int mg = tid & 63;
    const int bg = tid >> 6;

    float acc[4][4];
#pragma unroll
    for (int i = 0; i < 4; i++)
#pragma unroll
        for (int j = 0; j < 4; j++) acc[i][j] = 0.f;

    float4 ar[4];
    auto ldg_tile = [&](int dc) {
#pragma unroll
        for (int k = 0; k < 4; k++) {
            int t4 = tid + k * 256;
            int m  = t4 >> 2;
            int d4 = t4 & 3;
            ar[k] = *reinterpret_cast<const float4*>(
                &head_w[(size_t)(m0 + m) * ZDIM_ + dc * 16 + d4 * 4]);
        }
    };
    auto sts_tile = [&](int buf) {
#pragma unroll
        for (int k = 0; k < 4; k++) {
            int t4 = tid + k * 256;
            int m  = t4 >> 2;
            int d4 = t4 & 3;
            *reinterpret_cast<float4*>(&hw_s[buf][m * 20 + d4 * 4]) = ar[k];
        }
    };

    ldg_tile(0);
    sts_tile(0);
    ldg_tile(1);
    __syncthreads();

    for (int dc = 0; dc < 16; dc++) {
        const float* hb = hw_s[dc & 1];
#pragma unroll
        for (int d4 = 0; d4 < 4; d4++) {
            float hq[4][4];
#pragma unroll
            for (int i = 0; i < 4; i++)
                *reinterpret_cast<float4*>(hq[i]) =
                    *reinterpret_cast<const float4*>(&hb[(mg + 64 * i) * 20 + d4 * 4]);
            float zq[4][4];
#pragma unroll
            for (int e = 0; e < 4; e++)
                *reinterpret_cast<float4*>(zq[e]) =
                    *reinterpret_cast<const float4*>(&zt[(dc * 16 + d4 * 4 + e) * B_ + bg * 4]);
#pragma unroll
            for (int e = 0; e < 4; e++)
#pragma unroll
                for (int i = 0; i < 4; i++)
#pragma unroll
                    for (int j = 0; j < 4; j++)
                        acc[i][j] += hq[i][e] * zq[e][j];
        }
        if (dc < 15) {
            sts_tile((dc + 1) & 1);
            if (dc + 2 < 16) ldg_tile(dc + 2);
            __syncthreads();
        }
    }

    // scatter to fragment-order layout
#pragma unroll
    for (int i = 0; i < 4; i++) {
        int m   = m0 + mg + 64 * i;
        int oc  = m / 1152;
        int rem = m - oc * 1152;
        int ic  = rem / 9;
        int tap = rem - ic * 9;
        float bb = base_w[m] + head_b[m];

        int jc   = (ic >> 5) * 9 + tap;
        int k    = ic & 31;
        int ks   = k >> 3;
        int k8   = k & 7;
        int tile = oc >> 4;
        int m16  = oc & 15;
        int lane = (m16 & 7) * 4 + (k8 & 3);
        int reg  = (m16 >> 3) + 2 * (k8 >> 2);
        size_t off = (size_t)jc * 4096 + tile * 512 + ks * 128 + lane * 4 + reg;
#pragma unroll
        for (int j = 0; j < 4; j++) {
            int b = bg * 4 + j;
            g_w[((size_t)b * 36) * 4096 + off] = to_tf32(bb + acc[i][j]);
        }
    }
}

// ---------------------------------------------------------------------------
// Kernel 2: implicit-GEMM conv on mma.sync tf32 (HMMA).
// CTA tile: M=128 oc x N=128 px (2 rows x 64 cols) x K=1152 (36 chunks of 32).
// 8 warps 4x2: each 32 oc x 64 px.
// A: fragments loaded DIRECTLY from fragment-ordered g_w via LDG.128,
//    prefetched half-chunk ahead into registers. No A SMEM, no per-chunk
//    barrier — only 8 barriers total (xs rebuilds).
// B: direct from xs slab (tf32-rounded x), ic-stride 280 -> conflict-free.
// ---------------------------------------------------------------------------
__device__ __forceinline__ void mma_tf32(float* d, const uint32_t* a,
                                         uint32_t b0, uint32_t b1) {
    asm volatile(
        "mma.sync.aligned.m16n8k8.row.col.f32.tf32.tf32.f32 "
        "{%0,%1,%2,%3}, {%4,%5,%6,%7}, {%8,%9}, {%0,%1,%2,%3};"
        : "+f"(d[0]), "+f"(d[1]), "+f"(d[2]), "+f"(d[3])
        : "r"(a[0]), "r"(a[1]), "r"(a[2]), "r"(a[3]), "r"(b0), "r"(b1));
}

__global__ __launch_bounds__(256, 2) void conv_kernel(
    const float* __restrict__ x, float* __restrict__ out)
{
    __shared__ float xs[32 * 280];

    const int tid  = threadIdx.x;
    const int wid  = tid >> 5;
    const int lid  = tid & 31;
    const int g    = lid >> 2;        // 0..7
    const int tg   = lid & 3;         // 0..3
    const int wm   = wid & 3;         // oc quarter (32 oc)
    const int wn   = wid >> 2;        // px half (1 output row)
    const int pair = blockIdx.x;      // 0..31
    const int b    = blockIdx.y;      // 0..15
    const int r0   = pair * 2;

    const float* xb = x + (size_t)b * IC_ * 4096;
    // this warp's A-fragment base: [b][j][tile=wm*2+mt][ks][lane][reg]
    const float* wfrag = g_w + ((size_t)b * 36) * 4096 + (wm * 2) * 512 + lid * 4;

    float acc[2][8][4];
#pragma unroll
    for (int mt = 0; mt < 2; mt++)
#pragma unroll
        for (int nt = 0; nt < 8; nt++)
#pragma unroll
            for (int r = 0; r < 4; r++) acc[mt][nt][r] = 0.f;

    auto build_xs = [&](int icc) {
        for (int idx = tid; idx < 32 * 4 * 66; idx += 256) {
            int ic  = idx / 264;
            int rem = idx - ic * 264;
            int rr  = rem / 66;
            int cc  = rem - rr * 66;
            int gr  = r0 - 1 + rr;
            int gc  = cc - 1;
            float v = 0.f;
            if ((unsigned)gr < 64u && (unsigned)gc < 64u)
                v = xb[(size_t)(icc * 32 + ic) * 4096 + gr * 64 + gc];
            xs[ic * 280 + rr * 68 + cc] = to_tf32(v);
        }
    };

    float4 af[2][4];   // [mt][ks] — each float4 = {a0,a1,a2,a3}

    auto ldgA_half = [&](int j, int half) {
        const float* p = wfrag + (size_t)j * 4096 + half * 256;
#pragma unroll
        for (int mt = 0; mt < 2; mt++)
#pragma unroll
            for (int q = 0; q < 2; q++)
                af[mt][half * 2 + q] =
                    *reinterpret_cast<const float4*>(p + mt * 512 + q * 128);
    };

    auto do_ks = [&](int ks, const float* xw) {
        const int k0 = ks * 8 + tg;
        const float* xk0 = xw + k0 * 280;
        const float* xk1 = xk0 + 4 * 280;
        uint32_t a0[4], a1[4];
        a0[0] = __float_as_uint(af[0][ks].x); a0[1] = __float_as_uint(af[0][ks].y);
        a0[2] = __float_as_uint(af[0][ks].z); a0[3] = __float_as_uint(af[0][ks].w);
        a1[0] = __float_as_uint(af[1][ks].x); a1[1] = __float_as_uint(af[1][ks].y);
        a1[2] = __float_as_uint(af[1][ks].z); a1[3] = __float_as_uint(af[1][ks].w);
#pragma unroll
        for (int nt = 0; nt < 8; nt++) {
            uint32_t b0 = __float_as_uint(xk0[nt * 8]);
            uint32_t b1 = __float_as_uint(xk1[nt * 8]);
            mma_tf32(acc[0][nt], a0, b0, b1);
            mma_tf32(acc[1][nt], a1, b0, b1);
        }
    };

    // ---- prologue ----
    build_xs(0);
    ldgA_half(0, 0);
    ldgA_half(0, 1);
    __syncthreads();

    // ---- main loop: barrier-free inside each icc group of 9 chunks ----
    for (int icc = 0; icc < 4; icc++) {
#pragma unroll
        for (int tap = 0; tap < 9; tap++) {
            const int j  = icc * 9 + tap;
            const int kh = tap / 3;
            const int kw = tap - kh * 3;
            const float* xw = xs + (wn + kh) * 68 + kw + g;

            do_ks(0, xw);
            do_ks(1, xw);
            if (j + 1 < 36) ldgA_half(j + 1, 0);   // af[*][0..1] free now
            do_ks(2, xw);
            do_ks(3, xw);
            if (j + 1 < 36) ldgA_half(j + 1, 1);   // af[*][2..3] free now
        }
        if (icc + 1 < 4) {
            __syncthreads();           // all warps done reading xs
            build_xs(icc + 1);
            __syncthreads();
        }
    }

    // ---- epilogue: acc -> out[b][oc][px] ----
#pragma unroll
    for (int mt = 0; mt < 2; mt++) {
        int oc = wm * 32 + mt * 16 + g;
#pragma unroll
        for (int nt = 0; nt < 8; nt++) {
            int n  = wn * 64 + nt * 8 + 2 * tg;
            size_t base = ((size_t)b * OC_ + oc) * 4096 + pair * 128 + n;
            float2 v0 = make_float2(acc[mt][nt][0], acc[mt][nt][1]);
            float2 v1 = make_float2(acc[mt][nt][2], acc[mt][nt][3]);
            *reinterpret_cast<float2*>(out + base)            = v0;
            *reinterpret_cast<float2*>(out + base + 8 * 4096) = v1;
        }
    }
}

// ---------------------------------------------------------------------------
extern "C" void kernel_launch(void* const* d_in, const int* in_sizes, int n_in,
                              void* d_out, int out_size) {
    const float* x      = (const float*)d_in[0];
    const float* z      = (const float*)d_in[1];
    const float* base_w = (const float*)d_in[2];
    const float* head_w = (const float*)d_in[3];
    const float* head_b = (const float*)d_in[4];
    float* out = (float*)d_out;

    weight_kernel<<<WSIZE_ / 256, 256>>>(z, base_w, head_w, head_b);
    conv_kernel<<<dim3(32, 16), 256>>>(x, out);
}

// round 7
// speedup vs baseline: 3.1600x; 1.1001x over previous
#include <cuda_runtime.h>
#include <cstdint>

#define IC_   128
#define OC_   128
#define ZDIM_ 256
#define B_    16
#define WSIZE_ (OC_ * IC_ * 9)   // 147456

// Per-sample weights in m16n8k8 A-fragment order:
// [b][chunk j=icc*9+tap (36)][m16-tile (8)][ks (4)][lane (32)][reg (4)]
// => one chunk is 4096 floats = 16KB contiguous.
__device__ float g_w[(size_t)B_ * WSIZE_];

__device__ __forceinline__ float to_tf32(float v) {
    float o;
    asm("cvt.rna.tf32.f32 %0, %1;" : "=f"(o) : "f"(v));
    return o;
}

__device__ __forceinline__ uint32_t smem_u32(const void* p) {
    uint32_t a;
    asm("{ .reg .u64 t; cvta.to.shared.u64 t, %1; cvt.u32.u64 %0, t; }" : "=r"(a) : "l"(p));
    return a;
}

__device__ __forceinline__ void cp_async16(uint32_t dst, const void* src) {
    asm volatile("cp.async.cg.shared.global [%0], [%1], 16;" :: "r"(dst), "l"(src));
}

// ---------------------------------------------------------------------------
// Kernel 1: per-sample weight generation (fp32 GEMM on CUDA cores)
//   val = tf32_round(base_w[m] + head_b[m] + head_w[m] . z[b]),
//   scattered into fragment-order g_w.   (unchanged from R6: measured ~38us)
// ---------------------------------------------------------------------------
__global__ __launch_bounds__(256) void weight_kernel(
    const float* __restrict__ z, const float* __restrict__ base_w,
    const float* __restrict__ head_w, const float* __restrict__ head_b)
{
    __shared__ float zt[ZDIM_ * B_];        // z transposed: [d][b]
    __shared__ float hw_s[2][256 * 20];     // double-buffered, pitch 20 (16B-aligned)

    const int tid = threadIdx.x;
    const int m0  = blockIdx.x * 256;

    for (int i = tid; i < B_ * ZDIM_; i += 256) {
        int b = i >> 8;
        int d = i & 255;
        zt[d * B_ + b] = z[i];
    }

    const int mg = tid & 63;
    const int bg = tid >> 6;

    float acc[4][4];
#pragma unroll
    for (int i = 0; i < 4; i++)
#pragma unroll
        for (int j = 0; j < 4; j++) acc[i][j] = 0.f;

    float4 ar[4];
    auto ldg_tile = [&](int dc) {
#pragma unroll
        for (int k = 0; k < 4; k++) {
            int t4 = tid + k * 256;
            int m  = t4 >> 2;
            int d4 = t4 & 3;
            ar[k] = *reinterpret_cast<const float4*>(
                &head_w[(size_t)(m0 + m) * ZDIM_ + dc * 16 + d4 * 4]);
        }
    };
    auto sts_tile = [&](int buf) {
#pragma unroll
        for (int k = 0; k < 4; k++) {
            int t4 = tid + k * 256;
            int m  = t4 >> 2;
            int d4 = t4 & 3;
            *reinterpret_cast<float4*>(&hw_s[buf][m * 20 + d4 * 4]) = ar[k];
        }
    };

    ldg_tile(0);
    sts_tile(0);
    ldg_tile(1);
    __syncthreads();

    for (int dc = 0; dc < 16; dc++) {
        const float* hb = hw_s[dc & 1];
#pragma unroll
        for (int d4 = 0; d4 < 4; d4++) {
            float hq[4][4];
#pragma unroll
            for (int i = 0; i < 4; i++)
                *reinterpret_cast<float4*>(hq[i]) =
                    *reinterpret_cast<const float4*>(&hb[(mg + 64 * i) * 20 + d4 * 4]);
            float zq[4][4];
#pragma unroll
            for (int e = 0; e < 4; e++)
                *reinterpret_cast<float4*>(zq[e]) =
                    *reinterpret_cast<const float4*>(&zt[(dc * 16 + d4 * 4 + e) * B_ + bg * 4]);
#pragma unroll
            for (int e = 0; e < 4; e++)
#pragma unroll
                for (int i = 0; i < 4; i++)
#pragma unroll
                    for (int j = 0; j < 4; j++)
                        acc[i][j] += hq[i][e] * zq[e][j];
        }
        if (dc < 15) {
            sts_tile((dc + 1) & 1);
            if (dc + 2 < 16) ldg_tile(dc + 2);
            __syncthreads();
        }
    }

    // scatter to fragment-order layout
#pragma unroll
    for (int i = 0; i < 4; i++) {
        int m   = m0 + mg + 64 * i;
        int oc  = m / 1152;
        int rem = m - oc * 1152;
        int ic  = rem / 9;
        int tap = rem - ic * 9;
        float bb = base_w[m] + head_b[m];

        int jc   = (ic >> 5) * 9 + tap;
        int k    = ic & 31;
        int ks   = k >> 3;
        int k8   = k & 7;
        int tile = oc >> 4;
        int m16  = oc & 15;
        int lane = (m16 & 7) * 4 + (k8 & 3);
        int reg  = (m16 >> 3) + 2 * (k8 >> 2);
        size_t off = (size_t)jc * 4096 + tile * 512 + ks * 128 + lane * 4 + reg;
#pragma unroll
        for (int j = 0; j < 4; j++) {
            int b = bg * 4 + j;
            g_w[((size_t)b * 36) * 4096 + off] = to_tf32(bb + acc[i][j]);
        }
    }
}

// ---------------------------------------------------------------------------
// Kernel 2: implicit-GEMM conv on mma.sync tf32 (HMMA).
// CTA tile: M=128 oc x N=128 px (2 rows x 64 cols) x K=1152 (36 chunks of 32).
// 8 warps 4x2: each 32 oc x 64 px.
// A: fragment-ordered 16KB chunks streamed via cp.async, 3-stage SMEM ring,
//    ONE barrier per chunk; fragment read = single LDS.128 per (mt,ks).
// B: direct from xs slab (tf32-rounded x), ic-stride 280 -> conflict-free.
// SMEM floats: A stages [0, 12288), xs at 12288 (32*280=8960). 83KB dynamic.
// ---------------------------------------------------------------------------
#define XS_OFF    12288
#define SM_FLOATS (12288 + 32 * 280)

__device__ __forceinline__ void mma_tf32(float* d, const uint32_t* a,
                                         uint32_t b0, uint32_t b1) {
    asm volatile(
        "mma.sync.aligned.m16n8k8.row.col.f32.tf32.tf32.f32 "
        "{%0,%1,%2,%3}, {%4,%5,%6,%7}, {%8,%9}, {%0,%1,%2,%3};"
        : "+f"(d[0]), "+f"(d[1]), "+f"(d[2]), "+f"(d[3])
        : "r"(a[0]), "r"(a[1]), "r"(a[2]), "r"(a[3]), "r"(b0), "r"(b1));
}

__global__ __launch_bounds__(256, 2) void conv_kernel(
    const float* __restrict__ x, float* __restrict__ out)
{
    extern __shared__ float sm[];
    float* xs = sm + XS_OFF;
    const uint32_t smb = smem_u32(sm);

    const int tid  = threadIdx.x;
    const int wid  = tid >> 5;
    const int lid  = tid & 31;
    const int g    = lid >> 2;        // 0..7
    const int tg   = lid & 3;         // 0..3
    const int wm   = wid & 3;         // oc quarter (32 oc)
    const int wn   = wid >> 2;        // px half (1 output row)
    const int pair = blockIdx.x;      // 0..31
    const int b    = blockIdx.y;      // 0..15
    const int r0   = pair * 2;

    const float* xb = x + (size_t)b * IC_ * 4096;
    const float* wbase = g_w + ((size_t)b * 36) * 4096;

    float acc[2][8][4];
#pragma unroll
    for (int mt = 0; mt < 2; mt++)
#pragma unroll
        for (int nt = 0; nt < 8; nt++)
#pragma unroll
            for (int r = 0; r < 4; r++) acc[mt][nt][r] = 0.f;

    auto build_xs = [&](int icc) {
        for (int idx = tid; idx < 32 * 4 * 66; idx += 256) {
            int ic  = idx / 264;
            int rem = idx - ic * 264;
            int rr  = rem / 66;
            int cc  = rem - rr * 66;
            int gr  = r0 - 1 + rr;
            int gc  = cc - 1;
            float v = 0.f;
            if ((unsigned)gr < 64u && (unsigned)gc < 64u)
                v = xb[(size_t)(icc * 32 + ic) * 4096 + gr * 64 + gc];
            xs[ic * 280 + rr * 68 + cc] = to_tf32(v);
        }
    };

    // async copy of chunk j (16KB) into stage buffer
    auto cpA = [&](int j, int stage) {
        const float4* src = reinterpret_cast<const float4*>(wbase + (size_t)j * 4096) + tid;
        uint32_t dst = smb + stage * 16384 + tid * 16;
#pragma unroll
        for (int t = 0; t < 4; t++)
            cp_async16(dst + t * 4096, src + t * 256);
        asm volatile("cp.async.commit_group;" ::: "memory");
    };

    auto mma_chunk = [&](int stage, int kh, int kw) {
        const float* As = sm + stage * 4096 + (wm * 2) * 512 + lid * 4;
        const float* xw = xs + (wn + kh) * 68 + kw + g;
#pragma unroll
        for (int ks = 0; ks < 4; ks++) {
            float4 fa0 = *reinterpret_cast<const float4*>(As + ks * 128);
            float4 fa1 = *reinterpret_cast<const float4*>(As + 512 + ks * 128);
            uint32_t a0[4], a1[4];
            a0[0] = __float_as_uint(fa0.x); a0[1] = __float_as_uint(fa0.y);
            a0[2] = __float_as_uint(fa0.z); a0[3] = __float_as_uint(fa0.w);
            a1[0] = __float_as_uint(fa1.x); a1[1] = __float_as_uint(fa1.y);
            a1[2] = __float_as_uint(fa1.z); a1[3] = __float_as_uint(fa1.w);
            const int k0 = ks * 8 + tg;
            const float* xk0 = xw + k0 * 280;
            const float* xk1 = xk0 + 4 * 280;
#pragma unroll
            for (int nt = 0; nt < 8; nt++) {
                uint32_t b0 = __float_as_uint(xk0[nt * 8]);
                uint32_t b1 = __float_as_uint(xk1[nt * 8]);
                mma_tf32(acc[0][nt], a0, b0, b1);
                mma_tf32(acc[1][nt], a1, b0, b1);
            }
        }
    };

    // ---- prologue ----
    cpA(0, 0);
    cpA(1, 1);
    build_xs(0);
    asm volatile("cp.async.wait_group 1;" ::: "memory");
    __syncthreads();

    // ---- main loop: 3-stage cp.async ring, 1 barrier per chunk ----
    for (int icc = 0; icc < 4; icc++) {
#pragma unroll
        for (int tap = 0; tap < 9; tap++) {
            const int j  = icc * 9 + tap;
            const int kh = tap / 3;
            const int kw = tap - kh * 3;

            if (j + 2 < 36) cpA(j + 2, (j + 2) % 3);
            mma_chunk(j % 3, kh, kw);
            if (j + 2 < 36)
                asm volatile("cp.async.wait_group 1;" ::: "memory");
            else
                asm volatile("cp.async.wait_group 0;" ::: "memory");
            __syncthreads();

            if (tap == 8 && icc < 3) {
                build_xs(icc + 1);
                __syncthreads();
            }
        }
    }

    // ---- epilogue: acc -> out[b][oc][px] ----
#pragma unroll
    for (int mt = 0; mt < 2; mt++) {
        int oc = wm * 32 + mt * 16 + g;
#pragma unroll
        for (int nt = 0; nt < 8; nt++) {
            int n  = wn * 64 + nt * 8 + 2 * tg;
            size_t base = ((size_t)b * OC_ + oc) * 4096 + pair * 128 + n;
            float2 v0 = make_float2(acc[mt][nt][0], acc[mt][nt][1]);
            float2 v1 = make_float2(acc[mt][nt][2], acc[mt][nt][3]);
            *reinterpret_cast<float2*>(out + base)            = v0;
            *reinterpret_cast<float2*>(out + base + 8 * 4096) = v1;
        }
    }
}

// ---------------------------------------------------------------------------
extern "C" void kernel_launch(void* const* d_in, const int* in_sizes, int n_in,
                              void* d_out, int out_size) {
    const float* x      = (const float*)d_in[0];
    const float* z      = (const float*)d_in[1];
    const float* base_w = (const float*)d_in[2];
    const float* head_w = (const float*)d_in[3];
    const float* head_b = (const float*)d_in[4];
    float* out = (float*)d_out;

    static bool attr_set = false;
    if (!attr_set) {
        cudaFuncSetAttribute(conv_kernel,
                             cudaFuncAttributeMaxDynamicSharedMemorySize,
                             SM_FLOATS * 4);
        attr_set = true;
    }

    weight_kernel<<<WSIZE_ / 256, 256>>>(z, base_w, head_w, head_b);
    conv_kernel<<<dim3(32, 16), 256, SM_FLOATS * 4>>>(x, out);
}

// round 8
// speedup vs baseline: 3.3972x; 1.0751x over previous
#include <cuda_runtime.h>
#include <cstdint>

#define IC_   128
#define OC_   128
#define ZDIM_ 256
#define B_    16
#define WSIZE_ (OC_ * IC_ * 9)   // 147456

// Per-sample weights in m16n8k8 A-fragment order:
// [b][chunk j=icc*9+tap (36)][m16-tile (8)][ks (4)][lane (32)][reg (4)]
__device__ float g_w[(size_t)B_ * WSIZE_];

__device__ __forceinline__ float to_tf32(float v) {
    float o;
    asm("cvt.rna.tf32.f32 %0, %1;" : "=f"(o) : "f"(v));
    return o;
}

__device__ __forceinline__ uint32_t smem_u32(const void* p) {
    uint32_t a;
    asm("{ .reg .u64 t; cvta.to.shared.u64 t, %1; cvt.u32.u64 %0, t; }" : "=r"(a) : "l"(p));
    return a;
}

__device__ __forceinline__ void cp_async16(uint32_t dst, const void* src) {
    asm volatile("cp.async.cg.shared.global [%0], [%1], 16;" :: "r"(dst), "l"(src));
}

// inverse of the fragment scatter: fragment index F -> original row m
__device__ __forceinline__ int frag_to_m(int F) {
    int jc   = F >> 12;
    int rem  = F & 4095;
    int tile = rem >> 9;
    int rem2 = rem & 511;
    int ks   = rem2 >> 7;
    int lane = (rem2 >> 2) & 31;
    int reg  = rem2 & 3;
    int oc   = tile * 16 + (lane >> 2) + ((reg & 1) << 3);
    int k8   = (lane & 3) + ((reg >> 1) << 2);
    int icc  = jc / 9;
    int tap  = jc - icc * 9;
    int ic   = icc * 32 + ks * 8 + k8;
    return (oc * 128 + ic) * 9 + tap;
}

// ---------------------------------------------------------------------------
// Kernel 1: per-sample weight generation, fragment-contiguous output blocks.
// Block bid owns fragment range [bid*256, bid*256+256) for all 16 b.
// Thread (f64 = tid&63, bg = tid>>6): 4 consecutive F (float4) x 4 b.
// head_w rows read via precomputed row pointers (coalesced 64B segments);
// g_w writes fully float4-coalesced.
// ---------------------------------------------------------------------------
__global__ __launch_bounds__(256) void weight_kernel(
    const float* __restrict__ z, const float* __restrict__ base_w,
    const float* __restrict__ head_w, const float* __restrict__ head_b)
{
    __shared__ float zt[ZDIM_ * B_];        // z transposed: [d][b]
    __shared__ float hw_s[2][256 * 20];     // double-buffered, pitch 20

    const int tid   = threadIdx.x;
    const int Fbase = blockIdx.x * 256;

    for (int i = tid; i < B_ * ZDIM_; i += 256) {
        int b = i >> 8;
        int d = i & 255;
        zt[d * B_ + b] = z[i];
    }

    // loader setup: thread loads rows rho = (tid>>2) + 64k, float4 at d4l
    const int d4l  = tid & 3;
    const int rho0 = tid >> 2;
    const float* rowp[4];
    int sig[4];
#pragma unroll
    for (int k = 0; k < 4; k++) {
        int rho = rho0 + (k << 6);
        int m   = frag_to_m(Fbase + rho);
        rowp[k] = head_w + (size_t)m * ZDIM_ + d4l * 4;
        sig[k]  = (rho >> 2) + ((rho & 3) << 6);   // smem slot
    }

    const int f64 = tid & 63;
    const int bg  = tid >> 6;

    float acc[4][4];
#pragma unroll
    for (int r = 0; r < 4; r++)
#pragma unroll
        for (int j = 0; j < 4; j++) acc[r][j] = 0.f;

    float4 ar[4];
    auto ldg_tile = [&](int dc) {
#pragma unroll
        for (int k = 0; k < 4; k++)
            ar[k] = *reinterpret_cast<const float4*>(rowp[k] + dc * 16);
    };
    auto sts_tile = [&](int buf) {
#pragma unroll
        for (int k = 0; k < 4; k++)
            *reinterpret_cast<float4*>(&hw_s[buf][sig[k] * 20 + d4l * 4]) = ar[k];
    };

    ldg_tile(0);
    sts_tile(0);
    ldg_tile(1);
    __syncthreads();

    for (int dc = 0; dc < 16; dc++) {
        const float* hb = hw_s[dc & 1];
#pragma unroll
        for (int d4 = 0; d4 < 4; d4++) {
            float hq[4][4];
#pragma unroll
            for (int r = 0; r < 4; r++)
                *reinterpret_cast<float4*>(hq[r]) =
                    *reinterpret_cast<const float4*>(&hb[(f64 + (r << 6)) * 20 + d4 * 4]);
            float zq[4][4];
#pragma unroll
            for (int e = 0; e < 4; e++)
                *reinterpret_cast<float4*>(zq[e]) =
                    *reinterpret_cast<const float4*>(&zt[(dc * 16 + d4 * 4 + e) * B_ + bg * 4]);
#pragma unroll
            for (int e = 0; e < 4; e++)
#pragma unroll
                for (int r = 0; r < 4; r++)
#pragma unroll
                    for (int j = 0; j < 4; j++)
                        acc[r][j] += hq[r][e] * zq[e][j];
        }
        if (dc < 15) {
            sts_tile((dc + 1) & 1);
            if (dc + 2 < 16) ldg_tile(dc + 2);
            __syncthreads();
        }
    }

    float bb[4];
#pragma unroll
    for (int r = 0; r < 4; r++) {
        int m = frag_to_m(Fbase + f64 * 4 + r);
        bb[r] = base_w[m] + head_b[m];
    }
#pragma unroll
    for (int j = 0; j < 4; j++) {
        int b = bg * 4 + j;
        float4 o;
        o.x = to_tf32(bb[0] + acc[0][j]);
        o.y = to_tf32(bb[1] + acc[1][j]);
        o.z = to_tf32(bb[2] + acc[2][j]);
        o.w = to_tf32(bb[3] + acc[3][j]);
        *reinterpret_cast<float4*>(&g_w[(size_t)b * WSIZE_ + Fbase + f64 * 4]) = o;
    }
}

// ---------------------------------------------------------------------------
// Kernel 2: implicit-GEMM conv on mma.sync tf32 (HMMA).
// CTA tile: M=128 oc x N=128 px (2 rows x 64 cols) x K=1152 (36 chunks of 32).
// 8 warps 4x2: each 32 oc x 64 px.
// A: per-warp PRIVATE 2-stage cp.async buffer (warp copies exactly its own
//    1024 fragment floats per chunk). No CTA barriers inside chunk groups —
//    warps free-run; wait_group paces each warp individually.
// B: direct from xs slab (tf32-rounded x), ic-stride 280 -> conflict-free.
// SMEM floats: A private 8*2*1024 = 16384, xs at 16384 (8960). 99KB dynamic.
// ---------------------------------------------------------------------------
#define XS_OFF    16384
#define SM_FLOATS (16384 + 32 * 280)

__device__ __forceinline__ void mma_tf32(float* d, const uint32_t* a,
                                         uint32_t b0, uint32_t b1) {
    asm volatile(
        "mma.sync.aligned.m16n8k8.row.col.f32.tf32.tf32.f32 "
        "{%0,%1,%2,%3}, {%4,%5,%6,%7}, {%8,%9}, {%0,%1,%2,%3};"
        : "+f"(d[0]), "+f"(d[1]), "+f"(d[2]), "+f"(d[3])
        : "r"(a[0]), "r"(a[1]), "r"(a[2]), "r"(a[3]), "r"(b0), "r"(b1));
}

__global__ __launch_bounds__(256, 2) void conv_kernel(
    const float* __restrict__ x, float* __restrict__ out)
{
    extern __shared__ float sm[];
    float* xs = sm + XS_OFF;
    const uint32_t smb = smem_u32(sm);

    const int tid  = threadIdx.x;
    const int wid  = tid >> 5;
    const int lid  = tid & 31;
    const int g    = lid >> 2;        // 0..7
    const int tg   = lid & 3;         // 0..3
    const int wm   = wid & 3;         // oc quarter (32 oc)
    const int wn   = wid >> 2;        // output row within pair
    const int pair = blockIdx.x;      // 0..31
    const int b    = blockIdx.y;      // 0..15
    const int r0   = pair * 2;

    const float* xb    = x + (size_t)b * IC_ * 4096;
    const float* wbase = g_w + ((size_t)b * 36) * 4096;

    float acc[2][8][4];
#pragma unroll
    for (int mt = 0; mt < 2; mt++)
#pragma unroll
        for (int nt = 0; nt < 8; nt++)
#pragma unroll
            for (int r = 0; r < 4; r++) acc[mt][nt][r] = 0.f;

    auto build_xs = [&](int icc) {
        for (int idx = tid; idx < 32 * 4 * 66; idx += 256) {
            int ic  = idx / 264;
            int rem = idx - ic * 264;
            int rr  = rem / 66;
            int cc  = rem - rr * 66;
            int gr  = r0 - 1 + rr;
            int gc  = cc - 1;
            float v = 0.f;
            if ((unsigned)gr < 64u && (unsigned)gc < 64u)
                v = xb[(size_t)(icc * 32 + ic) * 4096 + gr * 64 + gc];
            xs[ic * 280 + rr * 68 + cc] = to_tf32(v);
        }
    };

    // per-warp private A copy: this warp's 1024 fragment floats of chunk j
    const uint32_t aw_dst0 = smb + (wid * 2048 + lid * 4) * 4;
    auto cpA = [&](int j) {
        const float* src = wbase + (size_t)j * 4096 + wm * 1024 + lid * 4;
        uint32_t dst = aw_dst0 + (j & 1) * 4096;
#pragma unroll
        for (int i = 0; i < 8; i++)
            cp_async16(dst + i * 512, src + i * 128);
        asm volatile("cp.async.commit_group;" ::: "memory");
    };

    auto mma_chunk = [&](int stage, int kh, int kw) {
        const float* As = sm + wid * 2048 + stage * 1024 + lid * 4;
        const float* xw = xs + (wn + kh) * 68 + kw + g;
#pragma unroll
        for (int ks = 0; ks < 4; ks++) {
            float4 fa0 = *reinterpret_cast<const float4*>(As + ks * 128);
            float4 fa1 = *reinterpret_cast<const float4*>(As + 512 + ks * 128);
            uint32_t a0[4], a1[4];
            a0[0] = __float_as_uint(fa0.x); a0[1] = __float_as_uint(fa0.y);
            a0[2] = __float_as_uint(fa0.z); a0[3] = __float_as_uint(fa0.w);
            a1[0] = __float_as_uint(fa1.x); a1[1] = __float_as_uint(fa1.y);
            a1[2] = __float_as_uint(fa1.z); a1[3] = __float_as_uint(fa1.w);
            const int k0 = ks * 8 + tg;
            const float* xk0 = xw + k0 * 280;
            const float* xk1 = xk0 + 4 * 280;
#pragma unroll
            for (int nt = 0; nt < 8; nt++) {
                uint32_t b0 = __float_as_uint(xk0[nt * 8]);
                uint32_t b1 = __float_as_uint(xk1[nt * 8]);
                mma_tf32(acc[0][nt], a0, b0, b1);
                mma_tf32(acc[1][nt], a1, b0, b1);
            }
        }
    };

    // ---- prologue ----
    cpA(0);
    cpA(1);
    build_xs(0);
    __syncthreads();

    // ---- main loop: NO CTA barriers inside icc groups ----
    for (int icc = 0; icc < 4; icc++) {
#pragma unroll
        for (int tap = 0; tap < 9; tap++) {
            const int j  = icc * 9 + tap;
            const int kh = tap / 3;
            const int kw = tap - kh * 3;

            if (j < 34)
                asm volatile("cp.async.wait_group 1;" ::: "memory");
            else
                asm volatile("cp.async.wait_group 0;" ::: "memory");

            mma_chunk(j & 1, kh, kw);

            if (j + 2 < 36) cpA(j + 2);
        }
        if (icc < 3) {
            __syncthreads();          // all warps done reading xs
            build_xs(icc + 1);
            __syncthreads();
        }
    }

    // ---- epilogue: acc -> out[b][oc][px] ----
#pragma unroll
    for (int mt = 0; mt < 2; mt++) {
        int oc = wm * 32 + mt * 16 + g;
#pragma unroll
        for (int nt = 0; nt < 8; nt++) {
            int n  = wn * 64 + nt * 8 + 2 * tg;
            size_t base = ((size_t)b * OC_ + oc) * 4096 + pair * 128 + n;
            float2 v0 = make_float2(acc[mt][nt][0], acc[mt][nt][1]);
            float2 v1 = make_float2(acc[mt][nt][2], acc[mt][nt][3]);
            *reinterpret_cast<float2*>(out + base)            = v0;
            *reinterpret_cast<float2*>(out + base + 8 * 4096) = v1;
        }
    }
}

// ---------------------------------------------------------------------------
extern "C" void kernel_launch(void* const* d_in, const int* in_sizes, int n_in,
                              void* d_out, int out_size) {
    const float* x      = (const float*)d_in[0];
    const float* z      = (const float*)d_in[1];
    const float* base_w = (const float*)d_in[2];
    const float* head_w = (const float*)d_in[3];
    const float* head_b = (const float*)d_in[4];
    float* out = (float*)d_out;

    static bool attr_set = false;
    if (!attr_set) {
        cudaFuncSetAttribute(conv_kernel,
                             cudaFuncAttributeMaxDynamicSharedMemorySize,
                             SM_FLOATS * 4);
        attr_set = true;
    }

    weight_kernel<<<WSIZE_ / 256, 256>>>(z, base_w, head_w, head_b);
    conv_kernel<<<dim3(32, 16), 256, SM_FLOATS * 4>>>(x, out);
}